// round 4
// baseline (speedup 1.0000x reference)
#include <cuda_runtime.h>
#include <cuda_bf16.h>
#include <cstdint>

// ---------------------------------------------------------------------------
// KNN candidate-refine, fused selection:
//   P1: data -> bf16 + row norms d2 (fused)
//   P2: X -> bf16
//   P3: bf16 mma.sync GEMM (cp.async double-buffered) with fused per-block
//       top-16 selection -> g_part (16 candidates / query / n-block)
//   P4: merge per-block candidates -> global approx top-16 per query
//   P5: exact fp32 rescore of 16 candidates -> top-10 -> mode -> out
// targets is int32 on device (JAX x64 disabled).
// ---------------------------------------------------------------------------

#define QDIM  512
#define NMAX  50000
#define QMAX  1024
#define NCAND 16
#define GBM   128
#define GBN   128
#define GBK   64
#define SSTR  72                 // smem row stride in bf16 (64 payload + 8 pad)
#define NBLKMAX ((NMAX + GBN - 1) / GBN)   // 391
#define BIGF  3.402823466e+38f

__device__ float         g_d2[NMAX];
__device__ __nv_bfloat16 g_xBF[(size_t)QMAX * QDIM];
__device__ __nv_bfloat16 g_dataBF[(size_t)NMAX * QDIM];
__device__ float         g_part_s[(size_t)QMAX * NBLKMAX * NCAND];  // 25.6 MB
__device__ int           g_part_i[(size_t)QMAX * NBLKMAX * NCAND];  // 25.6 MB
__device__ int           g_cand[QMAX * NCAND];

#define CP_ASYNC16(dst, src, sz)                                        \
    asm volatile("cp.async.cg.shared.global [%0], [%1], 16, %2;\n" ::   \
                 "r"(dst), "l"(src), "r"(sz))
#define CP_COMMIT()  asm volatile("cp.async.commit_group;\n")
#define CP_WAIT(n)   asm volatile("cp.async.wait_group %0;\n" ::"n"(n))

// ---------------- P1: data -> bf16 + norms (warp per row) ----------------
__global__ void knn_prep_data_kernel(const float* __restrict__ data, int N) {
    int gtid = blockIdx.x * blockDim.x + threadIdx.x;
    int row  = gtid >> 5;
    int lane = gtid & 31;
    if (row >= N) return;
    const float4* src = reinterpret_cast<const float4*>(data + (size_t)row * QDIM);
    uint2* dst = reinterpret_cast<uint2*>(g_dataBF + (size_t)row * QDIM);
    float s = 0.f;
#pragma unroll
    for (int i = 0; i < 4; i++) {
        float4 v = src[lane + i * 32];
        s += v.x * v.x + v.y * v.y + v.z * v.z + v.w * v.w;
        __nv_bfloat162 lo = __float22bfloat162_rn(make_float2(v.x, v.y));
        __nv_bfloat162 hi = __float22bfloat162_rn(make_float2(v.z, v.w));
        uint2 pk;
        pk.x = *reinterpret_cast<uint32_t*>(&lo);
        pk.y = *reinterpret_cast<uint32_t*>(&hi);
        dst[lane + i * 32] = pk;
    }
#pragma unroll
    for (int o = 16; o > 0; o >>= 1) s += __shfl_xor_sync(0xFFFFFFFFu, s, o);
    if (lane == 0) g_d2[row] = s;
}

// ---------------- P2: X -> bf16 ----------------
__global__ void knn_convert_kernel(const float* __restrict__ src,
                                   __nv_bfloat16* __restrict__ dst, int n4) {
    int i = blockIdx.x * blockDim.x + threadIdx.x;
    if (i >= n4) return;
    float4 v = reinterpret_cast<const float4*>(src)[i];
    __nv_bfloat162 lo = __float22bfloat162_rn(make_float2(v.x, v.y));
    __nv_bfloat162 hi = __float22bfloat162_rn(make_float2(v.z, v.w));
    uint2 pk;
    pk.x = *reinterpret_cast<uint32_t*>(&lo);
    pk.y = *reinterpret_cast<uint32_t*>(&hi);
    reinterpret_cast<uint2*>(dst)[i] = pk;
}

// ---------------- P3: GEMM + fused block top-16 ----------------
extern __shared__ char dynsm[];

__global__ __launch_bounds__(256, 2) void knn_gemm_bf16_kernel(int N, int nblk) {
    __nv_bfloat16* As = reinterpret_cast<__nv_bfloat16*>(dynsm);   // [2][GBM*SSTR]
    __nv_bfloat16* Bs = As + 2 * GBM * SSTR;                        // [2][GBN*SSTR]
    float*         Ssc = reinterpret_cast<float*>(dynsm);           // [64][133] alias
    __shared__ float s_d2[GBN];

    const int tid   = threadIdx.x;
    const int warp  = tid >> 5;
    const int lane  = tid & 31;
    const int g     = lane >> 2;
    const int t4    = lane & 3;
    const int qBase = blockIdx.y * GBM;
    const int nBase = blockIdx.x * GBN;

    const uint32_t sA = (uint32_t)__cvta_generic_to_shared(As);
    const uint32_t sB = (uint32_t)__cvta_generic_to_shared(Bs);

    float acc[16][4];
#pragma unroll
    for (int f = 0; f < 16; f++)
#pragma unroll
        for (int c = 0; c < 4; c++) acc[f][c] = 0.f;

    // async-load one K-stage into buffer (it & 1)
    auto issue = [&](int it) {
        const int kb  = it * GBK;
        const int buf = it & 1;
#pragma unroll
        for (int p = 0; p < 4; p++) {
            int lin = tid + p * 256;
            int row = lin >> 3;
            int c8  = lin & 7;
            uint32_t da = sA + (uint32_t)(buf * GBM * SSTR + row * SSTR + c8 * 8) * 2u;
            const void* ga = g_xBF + (size_t)(qBase + row) * QDIM + kb + c8 * 8;
            CP_ASYNC16(da, ga, 16);
            int n = nBase + row;
            int sz = (n < N) ? 16 : 0;
            int nc = (n < N) ? n : 0;
            uint32_t db = sB + (uint32_t)(buf * GBN * SSTR + row * SSTR + c8 * 8) * 2u;
            const void* gb = g_dataBF + (size_t)nc * QDIM + kb + c8 * 8;
            CP_ASYNC16(db, gb, sz);
        }
        CP_COMMIT();
    };

    issue(0);
    if (tid < GBN) {
        int n = nBase + tid;
        s_d2[tid] = (n < N) ? g_d2[n] : 0.f;
    }

    const int NT = QDIM / GBK;   // 8
    for (int it = 0; it < NT; it++) {
        if (it + 1 < NT) { issue(it + 1); CP_WAIT(1); }
        else             { CP_WAIT(0); }
        __syncthreads();

        const uint32_t* AsW =
            reinterpret_cast<const uint32_t*>(As + (it & 1) * GBM * SSTR);
        const uint32_t* BsW =
            reinterpret_cast<const uint32_t*>(Bs + (it & 1) * GBN * SSTR);

#pragma unroll
        for (int ks = 0; ks < GBK; ks += 16) {
            int arow0 = (warp * 16 + g) * (SSTR / 2);
            int arow8 = (warp * 16 + g + 8) * (SSTR / 2);
            int kw    = ks / 2 + t4;
            uint32_t a0 = AsW[arow0 + kw];
            uint32_t a1 = AsW[arow8 + kw];
            uint32_t a2 = AsW[arow0 + kw + 4];
            uint32_t a3 = AsW[arow8 + kw + 4];
#pragma unroll
            for (int f = 0; f < 16; f++) {
                int brow = (f * 8 + g) * (SSTR / 2);
                uint32_t b0 = BsW[brow + kw];
                uint32_t b1 = BsW[brow + kw + 4];
                asm volatile(
                    "mma.sync.aligned.m16n8k16.row.col.f32.bf16.bf16.f32 "
                    "{%0,%1,%2,%3}, {%4,%5,%6,%7}, {%8,%9}, {%0,%1,%2,%3};\n"
                    : "+f"(acc[f][0]), "+f"(acc[f][1]),
                      "+f"(acc[f][2]), "+f"(acc[f][3])
                    : "r"(a0), "r"(a1), "r"(a2), "r"(a3), "r"(b0), "r"(b1));
            }
        }
        __syncthreads();
    }

    // ---- fused epilogue: per-block top-16 per query, two passes of 64 q ----
    for (int p = 0; p < 2; p++) {
        __syncthreads();                 // smem (Ssc aliases tiles) free to reuse
        if ((warp >> 2) == p) {
            int ql = (warp & 3) * 16 + g;        // 0..55
#pragma unroll
            for (int f = 0; f < 16; f++) {
                int col = f * 8 + t4 * 2;
                Ssc[ql * 133 + col]           = acc[f][0];
                Ssc[ql * 133 + col + 1]       = acc[f][1];
                Ssc[(ql + 8) * 133 + col]     = acc[f][2];
                Ssc[(ql + 8) * 133 + col + 1] = acc[f][3];
            }
        }
        __syncthreads();

        if (tid < 128) {
            int q    = tid >> 1;
            int half = tid & 1;
            int qglob = qBase + p * 64 + q;

            float sc[NCAND]; int ix[NCAND];
#pragma unroll
            for (int j = 0; j < NCAND; j++) { sc[j] = BIGF; ix[j] = 0x7FFFFFFF; }

            // interleaved columns: half scans col = 2*i + half (bank friendly)
            for (int i = 0; i < 64; i++) {
                int col = 2 * i + half;
                int n   = nBase + col;
                if (n < N) {
                    float s = s_d2[col] - 2.0f * Ssc[q * 133 + col];
                    if (s < sc[NCAND - 1] ||
                        (s == sc[NCAND - 1] && n < ix[NCAND - 1])) {
                        float cs = s; int ci = n;
#pragma unroll
                        for (int j = 0; j < NCAND; j++) {
                            if (cs < sc[j] || (cs == sc[j] && ci < ix[j])) {
                                float tf = sc[j]; int ti = ix[j];
                                sc[j] = cs; ix[j] = ci;
                                cs = tf; ci = ti;
                            }
                        }
                    }
                }
            }

            // pair merge (half 0 <-> half 1) via shuffle
            float ps[NCAND]; int pi[NCAND];
#pragma unroll
            for (int j = 0; j < NCAND; j++) {
                ps[j] = __shfl_xor_sync(0xFFFFFFFFu, sc[j], 1);
                pi[j] = __shfl_xor_sync(0xFFFFFFFFu, ix[j], 1);
            }
            if (half == 0) {
                float ms[NCAND]; int mi[NCAND];
                int ia = 0, ib = 0;
#pragma unroll
                for (int t = 0; t < NCAND; t++) {
                    bool takeA = (sc[ia] < ps[ib]) ||
                                 (sc[ia] == ps[ib] && ix[ia] < pi[ib]);
                    if (takeA) { ms[t] = sc[ia]; mi[t] = ix[ia]; ia++; }
                    else       { ms[t] = ps[ib]; mi[t] = pi[ib]; ib++; }
                }
                size_t base = (size_t)qglob * ((size_t)nblk * NCAND)
                            + (size_t)blockIdx.x * NCAND;
#pragma unroll
                for (int j = 0; j < NCAND; j++) {
                    g_part_s[base + j] = ms[j];
                    g_part_i[base + j] = mi[j];
                }
            }
        }
    }
}

// ---------------- P4: merge per-block candidates -> approx top-16 ----------------
#define MTPB 256

__global__ __launch_bounds__(MTPB) void knn_merge_kernel(int nblk) {
    __shared__ float ss[MTPB][NCAND + 1];
    __shared__ int   si[MTPB][NCAND + 1];

    const int q   = blockIdx.x;
    const int tid = threadIdx.x;
    const int M   = nblk * NCAND;
    const size_t base = (size_t)q * M;

    float bs[NCAND]; int bi[NCAND];
#pragma unroll
    for (int j = 0; j < NCAND; j++) { bs[j] = BIGF; bi[j] = 0x7FFFFFFF; }

    for (int i = tid; i < M; i += MTPB) {
        float s = g_part_s[base + i];
        int   n = g_part_i[base + i];
        if (s < bs[NCAND - 1] || (s == bs[NCAND - 1] && n < bi[NCAND - 1])) {
            float cs = s; int ci = n;
#pragma unroll
            for (int j = 0; j < NCAND; j++) {
                if (cs < bs[j] || (cs == bs[j] && ci < bi[j])) {
                    float tf = bs[j]; int ti = bi[j];
                    bs[j] = cs; bi[j] = ci;
                    cs = tf; ci = ti;
                }
            }
        }
    }

#pragma unroll
    for (int j = 0; j < NCAND; j++) { ss[tid][j] = bs[j]; si[tid][j] = bi[j]; }
    ss[tid][NCAND] = BIGF;
    si[tid][NCAND] = 0x7FFFFFFF;

    for (int stride = MTPB / 2; stride > 0; stride >>= 1) {
        __syncthreads();
        if (tid < stride) {
            int ia = 0, ib = 0;
            float os[NCAND]; int oi[NCAND];
#pragma unroll
            for (int t = 0; t < NCAND; t++) {
                float va = ss[tid][ia], vb = ss[tid + stride][ib];
                int   xa = si[tid][ia], xb = si[tid + stride][ib];
                bool takeA = (va < vb) || (va == vb && xa < xb);
                if (takeA) { os[t] = va; oi[t] = xa; ia++; }
                else       { os[t] = vb; oi[t] = xb; ib++; }
            }
#pragma unroll
            for (int t = 0; t < NCAND; t++) { ss[tid][t] = os[t]; si[tid][t] = oi[t]; }
        }
    }
    __syncthreads();
    if (tid < NCAND) g_cand[q * NCAND + tid] = si[0][tid];
}

// ---------------- P5: exact fp32 refine + mode ----------------
#define TK 10

__global__ __launch_bounds__(128) void knn_refine_kernel(
    const float* __restrict__ X, const float* __restrict__ D,
    const int* __restrict__ targets, float* __restrict__ out) {
    __shared__ float rs[NCAND];
    __shared__ int   ri[NCAND];

    const int q = blockIdx.x;
    const int tid = threadIdx.x;
    const int warp = tid >> 5;
    const int lane = tid & 31;

    const float4* X4 = reinterpret_cast<const float4*>(X + (size_t)q * QDIM);

#pragma unroll
    for (int cc = 0; cc < 4; cc++) {
        int c = warp * 4 + cc;
        int n = g_cand[q * NCAND + c];
        const float4* D4 = reinterpret_cast<const float4*>(D + (size_t)n * QDIM);
        float s = 0.f;
#pragma unroll
        for (int j = 0; j < 4; j++) {
            float4 a = X4[lane + j * 32];
            float4 b = D4[lane + j * 32];
            s += a.x * b.x + a.y * b.y + a.z * b.z + a.w * b.w;
        }
#pragma unroll
        for (int o = 16; o > 0; o >>= 1) s += __shfl_xor_sync(0xFFFFFFFFu, s, o);
        if (lane == 0) { rs[c] = g_d2[n] - 2.0f * s; ri[c] = n; }
    }
    __syncthreads();

    if (tid == 0) {
        float sc[NCAND]; int id[NCAND];
#pragma unroll
        for (int i = 0; i < NCAND; i++) { sc[i] = rs[i]; id[i] = ri[i]; }
        int lab[TK];
#pragma unroll
        for (int t = 0; t < TK; t++) {
            int best = -1;
            float bv = BIGF; int bx = 0x7FFFFFFF;
#pragma unroll
            for (int i = 0; i < NCAND; i++) {
                if (sc[i] < bv || (sc[i] == bv && id[i] < bx)) {
                    bv = sc[i]; bx = id[i]; best = i;
                }
            }
            lab[t] = targets[id[best]];
            sc[best] = BIGF; id[best] = 0x7FFFFFFF;
        }
        int bestLab = 1 << 30, bestCnt = 0;
#pragma unroll
        for (int i = 0; i < TK; i++) {
            int c = 0;
#pragma unroll
            for (int j = 0; j < TK; j++) c += (lab[j] == lab[i]) ? 1 : 0;
            if (c > bestCnt || (c == bestCnt && lab[i] < bestLab)) {
                bestCnt = c; bestLab = lab[i];
            }
        }
        out[q] = (float)bestLab;
    }
}

// ---------------------------------------------------------------------------
extern "C" void kernel_launch(void* const* d_in, const int* in_sizes, int n_in,
                              void* d_out, int out_size) {
    const float* X       = (const float*)d_in[0];    // [1024, 512]
    const float* data    = (const float*)d_in[1];    // [50000, 512]
    const int*   targets = (const int*)d_in[2];      // [50000] int32
    float*       out     = (float*)d_out;            // [1024]

    const int N = in_sizes[2];             // 50000
    const int Q = in_sizes[0] / QDIM;      // 1024
    const int nblk = (N + GBN - 1) / GBN;  // 391

    static bool attr_done = false;
    if (!attr_done) {
        cudaFuncSetAttribute(knn_gemm_bf16_kernel,
                             cudaFuncAttributeMaxDynamicSharedMemorySize,
                             2 * (GBM + GBN) * SSTR * (int)sizeof(__nv_bfloat16));
        attr_done = true;
    }

    // P1: data -> bf16 + norms
    int pb = (N * 32 + 255) / 256;
    knn_prep_data_kernel<<<pb, 256>>>(data, N);

    // P2: X -> bf16
    __nv_bfloat16* xbf;
    cudaGetSymbolAddress((void**)&xbf, g_xBF);
    int nx4 = Q * QDIM / 4;
    knn_convert_kernel<<<(nx4 + 255) / 256, 256>>>(X, xbf, nx4);

    // P3: GEMM + fused block top-16
    dim3 grid(nblk, Q / GBM);
    size_t dynbytes = 2 * (GBM + GBN) * SSTR * sizeof(__nv_bfloat16);  // 73728
    knn_gemm_bf16_kernel<<<grid, 256, dynbytes>>>(N, nblk);

    // P4: merge candidates
    knn_merge_kernel<<<Q, MTPB>>>(nblk);

    // P5: exact refine + mode
    knn_refine_kernel<<<Q, 128>>>(X, data, targets, out);
}